// round 6
// baseline (speedup 1.0000x reference)
#include <cuda_runtime.h>

#define B_ 1024
#define T_ 512
#define C_ 64
#define START_ 62
#define STOP_ 63
#define NEG_INF_ (-10000.0f)
#define FULL_ 0xffffffffu

__device__ float g_part[B_];
__device__ unsigned int g_done = 0;

__device__ __forceinline__ unsigned long long fma2(unsigned long long a,
                                                   unsigned long long b,
                                                   unsigned long long c)
{
    unsigned long long d;
    asm("fma.rn.f32x2 %0, %1, %2, %3;" : "=l"(d) : "l"(a), "l"(b), "l"(c));
    return d;
}
__device__ __forceinline__ unsigned long long pack2(float lo, float hi)
{
    unsigned long long d;
    asm("mov.b64 %0, {%1, %2};" : "=l"(d) : "f"(lo), "f"(hi));
    return d;
}
__device__ __forceinline__ float2 unpack2(unsigned long long v)
{
    float lo, hi;
    asm("mov.b64 {%0, %1}, %2;" : "=f"(lo), "=f"(hi) : "l"(v));
    return make_float2(lo, hi);
}

// One warp per batch, 2 columns per lane. Block = 64 threads = 2 batches.
__global__ void __launch_bounds__(64) crf_fwd(const float* __restrict__ em,
                                              const float* __restrict__ trans,
                                              const int* __restrict__ tags,
                                              const int* __restrict__ mask,
                                              float* __restrict__ out)
{
    const int wid  = threadIdx.x >> 5;           // warp in block
    const int lane = threadIdx.x & 31;
    const int b    = blockIdx.x * 2 + wid;       // batch
    const int c0   = 2 * lane;
    const int c1   = 2 * lane + 1;

    // double-buffered p vector, one per warp
    __shared__ __align__(16) float s_p[2][2][C_];

    // E columns for my two states, packed over adjacent i:
    // ec0[k] = {exp(trans[2k][c0]), exp(trans[2k+1][c0])}
    unsigned long long ec0[C_ / 2], ec1[C_ / 2];
#pragma unroll
    for (int k = 0; k < C_ / 2; ++k) {
        ec0[k] = pack2(__expf(trans[(2 * k) * C_ + c0]),
                       __expf(trans[(2 * k + 1) * C_ + c0]));
        ec1[k] = pack2(__expf(trans[(2 * k) * C_ + c1]),
                       __expf(trans[(2 * k + 1) * C_ + c1]));
    }

    float alpha0 = (c0 == START_) ? 0.0f : NEG_INF_;
    float alpha1 = (c1 == START_) ? 0.0f : NEG_INF_;
    float ref = 0.0f;     // warp-uniform shift: cancels exactly in the recursion
    float gold = 0.0f;    // every lane tracks gold redundantly (uniform)
    int   prev = START_;

    const float* emb = em   + (size_t)b * T_ * C_;
    const int*   tgb = tags + (size_t)b * T_;
    const int*   mkb = mask + (size_t)b * T_;

    // depth-4 prefetch ring
    float2 embuf[4]; int tgbuf[4], mkbuf[4];
#pragma unroll
    for (int k = 0; k < 4; ++k) {
        embuf[k] = *reinterpret_cast<const float2*>(&emb[k * C_ + c0]);
        tgbuf[k] = tgb[k];
        mkbuf[k] = mkb[k];
    }

#pragma unroll 4
    for (int t = 0; t < T_; ++t) {
        const int sl  = t & 3;
        const int buf = t & 1;
        const float2 emv = embuf[sl];
        const int    tg  = tgbuf[sl];
        const int    mk  = mkbuf[sl];

        // prefetch t+4 (off critical path)
        float2 e_n = make_float2(0.f, 0.f); int tg_n = 0, mk_n = 0;
        if (t + 4 < T_) {
            e_n  = *reinterpret_cast<const float2*>(&emb[(size_t)(t + 4) * C_ + c0]);
            tg_n = tgb[t + 4];
            mk_n = mkb[t + 4];
        }

        // publish p pair for my two states
        float p0 = __expf(alpha0 - ref);
        float p1 = __expf(alpha1 - ref);
        *reinterpret_cast<float2*>(&s_p[wid][buf][c0]) = make_float2(p0, p1);
        __syncwarp();

        // gold: warp-uniform, branch-free (tg, mk, prev uniform across warp)
        {
            float sel = (tg & 1) ? emv.y : emv.x;             // uniform selector
            float et  = __shfl_sync(FULL_, sel, tg >> 1);     // emission at tag
            float g   = et + __ldg(&trans[prev * C_ + tg]);   // uniform L1 load
            gold += mk ? g : 0.0f;
            prev  = mk ? tg : prev;
        }

        // matvec: s_c = sum_i p_i * E[i][c]; 16 broadcast LDS.128, 64 fma2
        const ulonglong2* ps = reinterpret_cast<const ulonglong2*>(s_p[wid][buf]);
        unsigned long long a0 = 0ull, a1 = 0ull;   // col c0
        unsigned long long b0 = 0ull, b1 = 0ull;   // col c1
#pragma unroll
        for (int k = 0; k < 16; ++k) {
            ulonglong2 v = ps[k];
            a0 = fma2(v.x, ec0[2 * k + 0], a0);
            a1 = fma2(v.y, ec0[2 * k + 1], a1);
            b0 = fma2(v.x, ec1[2 * k + 0], b0);
            b1 = fma2(v.y, ec1[2 * k + 1], b1);
        }
        float2 fa0 = unpack2(a0), fa1 = unpack2(a1);
        float2 fb0 = unpack2(b0), fb1 = unpack2(b1);
        float s0 = fmaxf((fa0.x + fa0.y) + (fa1.x + fa1.y), 1e-30f);
        float s1 = fmaxf((fb0.x + fb0.y) + (fb1.x + fb1.y), 1e-30f);

        float na0 = ref + __logf(s0) + emv.x;
        float na1 = ref + __logf(s1) + emv.y;
        alpha0 = mk ? na0 : alpha0;
        alpha1 = mk ? na1 : alpha1;

        // refresh the uniform shift every 4 steps (drift bound ~52 << 88)
        if ((t & 3) == 3)
            ref = __shfl_sync(FULL_, alpha0, 0);

        embuf[sl] = e_n; tgbuf[sl] = tg_n; mkbuf[sl] = mk_n;
    }

    // ---- final LSE over 64 states (warp-local, exact) ----
    float v0 = alpha0 + trans[c0 * C_ + STOP_];
    float v1 = alpha1 + trans[c1 * C_ + STOP_];
    float m = fmaxf(v0, v1);
#pragma unroll
    for (int o = 16; o > 0; o >>= 1)
        m = fmaxf(m, __shfl_xor_sync(FULL_, m, o));
    float ex = __expf(v0 - m) + __expf(v1 - m);
#pragma unroll
    for (int o = 16; o > 0; o >>= 1)
        ex += __shfl_xor_sync(FULL_, ex, o);

    unsigned int ticket = 0;
    if (lane == 0) {
        float logZ = m + __logf(ex);
        g_part[b] = logZ - (gold + trans[prev * C_ + STOP_]);
        __threadfence();
        ticket = atomicAdd(&g_done, 1u);
    }
    // last warp to finish does the deterministic mean
    int last = __shfl_sync(FULL_, (int)(ticket == (unsigned)(B_ - 1)), 0);
    if (last) {
        __threadfence();
        double acc = 0.0;
        for (int i = lane; i < B_; i += 32) acc += (double)g_part[i];  // fixed order
#pragma unroll
        for (int o = 16; o > 0; o >>= 1)
            acc += __shfl_down_sync(FULL_, acc, o);                    // fixed tree
        if (lane == 0) {
            out[0] = (float)(acc / (double)B_);
            g_done = 0;   // reset for next graph replay
        }
    }
}

extern "C" void kernel_launch(void* const* d_in, const int* in_sizes, int n_in,
                              void* d_out, int out_size)
{
    const float* em    = (const float*)d_in[0];
    const float* trans = (const float*)d_in[1];
    const int*   tags  = (const int*)d_in[2];
    const int*   mask  = (const int*)d_in[3];

    crf_fwd<<<B_ / 2, 64>>>(em, trans, tags, mask, (float*)d_out);
    (void)in_sizes; (void)n_in; (void)out_size;
}

// round 7
// speedup vs baseline: 1.0105x; 1.0105x over previous
#include <cuda_runtime.h>

#define B_ 1024
#define T_ 512
#define C_ 64
#define START_ 62
#define STOP_ 63
#define NEG_INF_ (-10000.0f)
#define FULL_ 0xffffffffu

__device__ float g_part[B_];
__device__ unsigned int g_done = 0;

__device__ __forceinline__ unsigned long long fma2(unsigned long long a,
                                                   unsigned long long b,
                                                   unsigned long long c)
{
    unsigned long long d;
    asm("fma.rn.f32x2 %0, %1, %2, %3;" : "=l"(d) : "l"(a), "l"(b), "l"(c));
    return d;
}
__device__ __forceinline__ unsigned long long pack2(float lo, float hi)
{
    unsigned long long d;
    asm("mov.b64 %0, {%1, %2};" : "=l"(d) : "f"(lo), "f"(hi));
    return d;
}
__device__ __forceinline__ float2 unpack2(unsigned long long v)
{
    float lo, hi;
    asm("mov.b64 {%0, %1}, %2;" : "=f"(lo), "=f"(hi) : "l"(v));
    return make_float2(lo, hi);
}

// One warp per batch, 2 columns per lane. Block = 64 threads = 2 batches.
__global__ void __launch_bounds__(64) crf_fwd(const float* __restrict__ em,
                                              const float* __restrict__ trans,
                                              const int* __restrict__ tags,
                                              const int* __restrict__ mask,
                                              float* __restrict__ out)
{
    const int wid  = threadIdx.x >> 5;           // warp in block
    const int lane = threadIdx.x & 31;
    const int b    = blockIdx.x * 2 + wid;       // batch
    const int c0   = 2 * lane;
    const int c1   = 2 * lane + 1;

    // double-buffered p vector, one per warp
    __shared__ __align__(16) float s_p[2][2][C_];

    // E columns for my two states, packed over adjacent i:
    // ec0[k] = {exp(trans[2k][c0]), exp(trans[2k+1][c0])}
    unsigned long long ec0[C_ / 2], ec1[C_ / 2];
#pragma unroll
    for (int k = 0; k < C_ / 2; ++k) {
        ec0[k] = pack2(__expf(trans[(2 * k) * C_ + c0]),
                       __expf(trans[(2 * k + 1) * C_ + c0]));
        ec1[k] = pack2(__expf(trans[(2 * k) * C_ + c1]),
                       __expf(trans[(2 * k + 1) * C_ + c1]));
    }

    float alpha0 = (c0 == START_) ? 0.0f : NEG_INF_;
    float alpha1 = (c1 == START_) ? 0.0f : NEG_INF_;
    float ref = 0.0f;     // warp-uniform shift: cancels exactly in the recursion
    float gold = 0.0f;    // every lane tracks gold redundantly (uniform)
    int   prev = START_;

    const float* emb = em   + (size_t)b * T_ * C_;
    const int*   tgb = tags + (size_t)b * T_;
    const int*   mkb = mask + (size_t)b * T_;

    // depth-4 prefetch ring
    float2 embuf[4]; int tgbuf[4], mkbuf[4];
#pragma unroll
    for (int k = 0; k < 4; ++k) {
        embuf[k] = *reinterpret_cast<const float2*>(&emb[k * C_ + c0]);
        tgbuf[k] = tgb[k];
        mkbuf[k] = mkb[k];
    }

#pragma unroll 4
    for (int t = 0; t < T_; ++t) {
        const int sl  = t & 3;
        const int buf = t & 1;
        const float2 emv = embuf[sl];
        const int    tg  = tgbuf[sl];
        const int    mk  = mkbuf[sl];

        // prefetch t+4 (off critical path)
        float2 e_n = make_float2(0.f, 0.f); int tg_n = 0, mk_n = 0;
        if (t + 4 < T_) {
            e_n  = *reinterpret_cast<const float2*>(&emb[(size_t)(t + 4) * C_ + c0]);
            tg_n = tgb[t + 4];
            mk_n = mkb[t + 4];
        }

        // publish p pair for my two states
        float p0 = __expf(alpha0 - ref);
        float p1 = __expf(alpha1 - ref);
        *reinterpret_cast<float2*>(&s_p[wid][buf][c0]) = make_float2(p0, p1);
        __syncwarp();

        // gold: warp-uniform, branch-free (tg, mk, prev uniform across warp)
        {
            float sel = (tg & 1) ? emv.y : emv.x;             // uniform selector
            float et  = __shfl_sync(FULL_, sel, tg >> 1);     // emission at tag
            float g   = et + __ldg(&trans[prev * C_ + tg]);   // uniform L1 load
            gold += mk ? g : 0.0f;
            prev  = mk ? tg : prev;
        }

        // matvec: s_c = sum_i p_i * E[i][c]; 16 broadcast LDS.128, 64 fma2
        const ulonglong2* ps = reinterpret_cast<const ulonglong2*>(s_p[wid][buf]);
        unsigned long long a0 = 0ull, a1 = 0ull;   // col c0
        unsigned long long b0 = 0ull, b1 = 0ull;   // col c1
#pragma unroll
        for (int k = 0; k < 16; ++k) {
            ulonglong2 v = ps[k];
            a0 = fma2(v.x, ec0[2 * k + 0], a0);
            a1 = fma2(v.y, ec0[2 * k + 1], a1);
            b0 = fma2(v.x, ec1[2 * k + 0], b0);
            b1 = fma2(v.y, ec1[2 * k + 1], b1);
        }
        float2 fa0 = unpack2(a0), fa1 = unpack2(a1);
        float2 fb0 = unpack2(b0), fb1 = unpack2(b1);
        float s0 = fmaxf((fa0.x + fa0.y) + (fa1.x + fa1.y), 1e-30f);
        float s1 = fmaxf((fb0.x + fb0.y) + (fb1.x + fb1.y), 1e-30f);

        float na0 = ref + __logf(s0) + emv.x;
        float na1 = ref + __logf(s1) + emv.y;
        alpha0 = mk ? na0 : alpha0;
        alpha1 = mk ? na1 : alpha1;

        // refresh the uniform shift every 4 steps (drift bound ~52 << 88)
        if ((t & 3) == 3)
            ref = __shfl_sync(FULL_, alpha0, 0);

        embuf[sl] = e_n; tgbuf[sl] = tg_n; mkbuf[sl] = mk_n;
    }

    // ---- final LSE over 64 states (warp-local, exact) ----
    float v0 = alpha0 + trans[c0 * C_ + STOP_];
    float v1 = alpha1 + trans[c1 * C_ + STOP_];
    float m = fmaxf(v0, v1);
#pragma unroll
    for (int o = 16; o > 0; o >>= 1)
        m = fmaxf(m, __shfl_xor_sync(FULL_, m, o));
    float ex = __expf(v0 - m) + __expf(v1 - m);
#pragma unroll
    for (int o = 16; o > 0; o >>= 1)
        ex += __shfl_xor_sync(FULL_, ex, o);

    unsigned int ticket = 0;
    if (lane == 0) {
        float logZ = m + __logf(ex);
        g_part[b] = logZ - (gold + trans[prev * C_ + STOP_]);
        __threadfence();
        ticket = atomicAdd(&g_done, 1u);
    }
    // last warp to finish does the deterministic mean
    int last = __shfl_sync(FULL_, (int)(ticket == (unsigned)(B_ - 1)), 0);
    if (last) {
        __threadfence();
        double acc = 0.0;
        for (int i = lane; i < B_; i += 32) acc += (double)g_part[i];  // fixed order
#pragma unroll
        for (int o = 16; o > 0; o >>= 1)
            acc += __shfl_down_sync(FULL_, acc, o);                    // fixed tree
        if (lane == 0) {
            out[0] = (float)(acc / (double)B_);
            g_done = 0;   // reset for next graph replay
        }
    }
}

extern "C" void kernel_launch(void* const* d_in, const int* in_sizes, int n_in,
                              void* d_out, int out_size)
{
    const float* em    = (const float*)d_in[0];
    const float* trans = (const float*)d_in[1];
    const int*   tags  = (const int*)d_in[2];
    const int*   mask  = (const int*)d_in[3];

    crf_fwd<<<B_ / 2, 64>>>(em, trans, tags, mask, (float*)d_out);
    (void)in_sizes; (void)n_in; (void)out_size;
}